// round 5
// baseline (speedup 1.0000x reference)
#include <cuda_runtime.h>
#include <math.h>

#define NB    32
#define NF    500
#define FEAT  256
#define COUT  2
#define CIN   2
#define KK    16
#define FRAME 160
#define OVL   40
#define NSAMP (NF * FRAME)          // 80000
#define NFILT (COUT * CIN * KK)     // 64

#define GAIN_A 0.69077552789821368f
#define SG     0.50118723362727224f
#define OMSG   0.49881276637272776f

typedef unsigned long long u64;

__device__ __forceinline__ u64 pack2(float lo, float hi) {
    u64 r;
    asm("mov.b64 %0, {%1, %2};" : "=l"(r) : "f"(lo), "f"(hi));
    return r;
}
__device__ __forceinline__ void unpack2(u64 v, float& lo, float& hi) {
    asm("mov.b64 {%0, %1}, %2;" : "=f"(lo), "=f"(hi) : "l"(v));
}
__device__ __forceinline__ void ffma2(u64& d, u64 a, u64 b) {
    asm("fma.rn.f32x2 %0, %1, %2, %0;" : "+l"(d) : "l"(a), "l"(b));
}

// Per-frame filters: [(b*NF+f)*64 + cout*32 + cin*16 + k]
__device__ float g_w[(size_t)NB * NF * NFILT];

// ===========================================================================
// Kernel A: filter GEMM (R3 structure) with f32x2-paired main loop.
// Block = 128 rows x 64 outs, thread tile 8 rows x (2 f32x2 col-pairs).
// ===========================================================================
#define TBF 128
#define FSTRIDE4 65                  // fs row stride in float4 (260 floats)
#define WSTRIDE  68                  // even -> u64 stride 34

__global__ void __launch_bounds__(256) filt_kernel(
    const float* __restrict__ feat,
    const float* __restrict__ ckw,
    const float* __restrict__ ckb,
    const float* __restrict__ fgw,
    const float* __restrict__ fgb)
{
    extern __shared__ float sm[];
    float*  fs   = sm;                                   // [128][260]
    float*  Wt   = sm + TBF * 260;                       // [256][68]
    float*  gg   = Wt + 256 * WSTRIDE;
    float*  invn = gg + TBF * 2;
    float*  gain = invn + TBF * 2;
    float4* fs4  = (float4*)fs;

    int tid = threadIdx.x;
    int bf0 = blockIdx.x * TBF;

    const float4* feat4 = (const float4*)feat;
    for (int i = tid; i < TBF * 64; i += 256) {
        int r = i >> 6, c4 = i & 63;
        fs4[r * FSTRIDE4 + c4] = feat4[(size_t)(bf0 + r) * 64 + c4];
    }
    for (int i = tid; i < 64 * 256; i += 256) {
        int o = i >> 8, fe = i & 255;
        Wt[fe * WSTRIDE + o] = ckw[i];
    }
    {
        int fe = tid;
        Wt[fe * WSTRIDE + 64] = 0.f; Wt[fe * WSTRIDE + 65] = 0.f;
        Wt[fe * WSTRIDE + 66] = 0.f; Wt[fe * WSTRIDE + 67] = 0.f;
    }
    __syncthreads();

    int ogrp = tid & 15, rgrp = tid >> 4;
    int o0 = ogrp * 4, r0 = rgrp * 8;

    u64 accP[8][2];
    #pragma unroll
    for (int i = 0; i < 8; ++i) { accP[i][0] = 0ull; accP[i][1] = 0ull; }

    const float4* fsp = fs4 + r0 * FSTRIDE4;
    const u64*    wt8 = (const u64*)Wt;
    int wbase = o0 >> 1;                         // u64 col offset

    #pragma unroll 4
    for (int fe4 = 0; fe4 < 64; ++fe4) {
        float4 fv[8];
        #pragma unroll
        for (int i = 0; i < 8; ++i) fv[i] = fsp[i * FSTRIDE4 + fe4];
        u64 w0a = wt8[(4 * fe4 + 0) * 34 + wbase];
        u64 w0b = wt8[(4 * fe4 + 0) * 34 + wbase + 1];
        u64 w1a = wt8[(4 * fe4 + 1) * 34 + wbase];
        u64 w1b = wt8[(4 * fe4 + 1) * 34 + wbase + 1];
        u64 w2a = wt8[(4 * fe4 + 2) * 34 + wbase];
        u64 w2b = wt8[(4 * fe4 + 2) * 34 + wbase + 1];
        u64 w3a = wt8[(4 * fe4 + 3) * 34 + wbase];
        u64 w3b = wt8[(4 * fe4 + 3) * 34 + wbase + 1];
        #pragma unroll
        for (int i = 0; i < 8; ++i) {
            u64 fx = pack2(fv[i].x, fv[i].x);
            u64 fy = pack2(fv[i].y, fv[i].y);
            u64 fz = pack2(fv[i].z, fv[i].z);
            u64 fw = pack2(fv[i].w, fv[i].w);
            ffma2(accP[i][0], fx, w0a); ffma2(accP[i][1], fx, w0b);
            ffma2(accP[i][0], fy, w1a); ffma2(accP[i][1], fy, w1b);
            ffma2(accP[i][0], fz, w2a); ffma2(accP[i][1], fz, w2b);
            ffma2(accP[i][0], fw, w3a); ffma2(accP[i][1], fw, w3b);
        }
    }

    // ---- gain logits ----
    {
        int r = tid >> 1, c = tid & 1;
        const float4* fr = fs4 + r * FSTRIDE4;
        const float4* gw = (const float4*)fgw + c * 64;
        float s = 0.f;
        #pragma unroll 4
        for (int q = 0; q < 64; ++q) {
            float4 a = fr[q];
            float4 b = __ldg(&gw[q]);
            s += a.x * b.x + a.y * b.y + a.z * b.z + a.w * b.w;
        }
        gg[r * 2 + c] = s + __ldg(&fgb[c]);
    }
    __syncthreads();

    // ---- raw (with bias) into reused fs region ----
    float* raw = fs;                  // [128][68]
    #pragma unroll
    for (int i = 0; i < 8; ++i) {
        float v0, v1, v2, v3;
        unpack2(accP[i][0], v0, v1);
        unpack2(accP[i][1], v2, v3);
        raw[(r0 + i) * WSTRIDE + o0 + 0] = v0 + __ldg(&ckb[o0 + 0]);
        raw[(r0 + i) * WSTRIDE + o0 + 1] = v1 + __ldg(&ckb[o0 + 1]);
        raw[(r0 + i) * WSTRIDE + o0 + 2] = v2 + __ldg(&ckb[o0 + 2]);
        raw[(r0 + i) * WSTRIDE + o0 + 3] = v3 + __ldg(&ckb[o0 + 3]);
    }
    __syncthreads();

    {
        int r = tid >> 1, c = tid & 1;
        float ss = 0.f;
        #pragma unroll
        for (int i = 0; i < 32; ++i) {
            float v = raw[r * WSTRIDE + c * 32 + i];
            ss += v * v;
        }
        invn[r * 2 + c] = 1.0f / (1e-6f + sqrtf(ss));
        gain[r * 2 + c] = expf(GAIN_A * tanhf(gg[r * 2 + c]));
    }
    __syncthreads();

    for (int idx = tid; idx < TBF * NFILT; idx += 256) {
        int r = idx >> 6, o = idx & 63;
        int co = o >> 5;
        float v = SG * raw[r * WSTRIDE + o] * invn[r * 2 + co];
        if ((o & 15) == 7) v += OMSG;
        g_w[(size_t)(bf0 + r) * NFILT + o] = v * gain[r * 2 + co];
    }
}

// ===========================================================================
// Kernel B: conv + overlap-add, f32x2 everywhere.
// Head: lane -> 5 outputs; m-pairs (0,1),(2,3) use dup-weight pairs {w,w};
// output 4 paired over cout via co-interleaved weight pairs {w_co0,w_co1}.
// Tail: cooperative (j=lane, then j=32+lane on 8 lanes), co-paired FFMA2.
// FPB=10, 320 threads, 3 blocks/SM.
// ===========================================================================
#define FPB  10
#define NEED (FPB * FRAME + 16)      // 1616
#define XPAD 1624

__global__ void __launch_bounds__(FPB * 32, 3) conv_kernel(
    const float* __restrict__ x,
    const float* __restrict__ owin,
    float* __restrict__ out)
{
    __shared__ __align__(16) float xs[CIN][XPAD];
    __shared__ __align__(8) float2 wdup[FPB + 1][COUT][CIN][KK]; // {w,w}
    __shared__ __align__(8) float2 wcop[FPB + 1][CIN][KK];       // {w0,w1}
    __shared__ float tb[FPB][COUT][OVL];
    __shared__ __align__(16) float ob[FPB][COUT][FRAME];
    __shared__ float w1s[OVL], w2s[OVL];

    const int NT = FPB * 32;
    int f0 = blockIdx.x * FPB;
    int b  = blockIdx.y;
    int tid  = threadIdx.x;
    int lane = tid & 31;
    int w    = tid >> 5;

    // ---- x window ----
    const float* xb = x + (size_t)b * CIN * NSAMP;
    if (f0 == 0) {
        if (tid < 16) { xs[0][tid] = 0.f; xs[1][tid] = 0.f; }
        const int N4 = (NEED - 16) / 4;
        for (int i = tid; i < CIN * N4; i += NT) {
            int ci = i / N4, q = i - ci * N4;
            ((float4*)(xs[ci] + 16))[q] =
                ((const float4*)(xb + (size_t)ci * NSAMP))[q];
        }
    } else {
        int base = f0 * FRAME - 16;
        const int N4 = NEED / 4;
        for (int i = tid; i < CIN * N4; i += NT) {
            int ci = i / N4, q = i - ci * N4;
            ((float4*)xs[ci])[q] =
                ((const float4*)(xb + (size_t)ci * NSAMP + base))[q];
        }
    }
    // ---- filter tables ----
    for (int i = tid; i < (FPB + 1) * NFILT; i += NT) {
        int fr = i >> 6, o = i & 63;
        int fi = f0 - 1 + fr;
        float v = (fi >= 0) ? g_w[((size_t)b * NF + fi) * NFILT + o] : 0.f;
        int co = o >> 5, ci = (o >> 4) & 1, k = o & 15;
        wdup[fr][co][ci][k] = make_float2(v, v);
    }
    for (int i = tid; i < (FPB + 1) * CIN * KK; i += NT) {
        int fr = i >> 5, rem = i & 31;
        int ci = rem >> 4, k = rem & 15;
        int fi = f0 - 1 + fr;
        float v0 = 0.f, v1 = 0.f;
        if (fi >= 0) {
            size_t rowp = ((size_t)b * NF + fi) * NFILT;
            v0 = g_w[rowp + ci * 16 + k];
            v1 = g_w[rowp + 32 + ci * 16 + k];
        }
        wcop[fr][ci][k] = make_float2(v0, v1);
    }
    if (tid < OVL) {
        w2s[tid] = owin[tid];
        w1s[tid] = owin[OVL - 1 - tid];
    }
    __syncthreads();

    int j0 = 5 * lane;
    int sb = w * FRAME + 16;

    // ---- head ----
    u64 A01[COUT] = {0ull, 0ull};      // outputs m=0,1 per cout
    u64 A23[COUT] = {0ull, 0ull};      // outputs m=2,3 per cout
    u64 A4 = 0ull;                     // output m=4, paired over cout

    #pragma unroll
    for (int ci = 0; ci < CIN; ++ci) {
        float xw[20];
        #pragma unroll
        for (int i = 0; i < 20; ++i)
            xw[i] = xs[ci][sb + j0 - 15 + i];
        const u64* wd0 = (const u64*)&wdup[w + 1][0][ci][0];
        const u64* wd1 = (const u64*)&wdup[w + 1][1][ci][0];
        const u64* wcp = (const u64*)&wcop[w + 1][ci][0];
        #pragma unroll
        for (int k = 0; k < KK; ++k) {
            u64 p0 = pack2(xw[15 - k], xw[16 - k]);
            u64 p2 = pack2(xw[17 - k], xw[18 - k]);
            u64 p4 = pack2(xw[19 - k], xw[19 - k]);
            u64 q0 = wd0[k], q1 = wd1[k];
            ffma2(A01[0], p0, q0);
            ffma2(A23[0], p2, q0);
            ffma2(A01[1], p0, q1);
            ffma2(A23[1], p2, q1);
            ffma2(A4, p4, wcp[k]);
        }
    }
    float a0[5], a1[5];
    unpack2(A01[0], a0[0], a0[1]);
    unpack2(A23[0], a0[2], a0[3]);
    unpack2(A01[1], a1[0], a1[1]);
    unpack2(A23[1], a1[2], a1[3]);
    unpack2(A4, a0[4], a1[4]);

    // ---- tail round 1: j = lane (all lanes; j < 40 always) ----
    {
        u64 T = 0ull;
        #pragma unroll
        for (int ci = 0; ci < CIN; ++ci) {
            float tw[16];
            #pragma unroll
            for (int i = 0; i < 16; ++i)
                tw[i] = xs[ci][sb + lane - 15 + i];
            const u64* wcp = (const u64*)&wcop[w][ci][0];
            #pragma unroll
            for (int k = 0; k < KK; ++k) {
                u64 p = pack2(tw[15 - k], tw[15 - k]);
                ffma2(T, p, wcp[k]);
            }
        }
        float t0, t1;
        unpack2(T, t0, t1);
        tb[w][0][lane] = t0;
        tb[w][1][lane] = t1;
    }
    // ---- tail round 2: j = 32 + lane (lanes 0-7) ----
    if (lane < 8) {
        int j = 32 + lane;
        u64 T = 0ull;
        #pragma unroll
        for (int ci = 0; ci < CIN; ++ci) {
            float tw[16];
            #pragma unroll
            for (int i = 0; i < 16; ++i)
                tw[i] = xs[ci][sb + j - 15 + i];
            const u64* wcp = (const u64*)&wcop[w][ci][0];
            #pragma unroll
            for (int k = 0; k < KK; ++k) {
                u64 p = pack2(tw[15 - k], tw[15 - k]);
                ffma2(T, p, wcp[k]);
            }
        }
        float t0, t1;
        unpack2(T, t0, t1);
        tb[w][0][j] = t0;
        tb[w][1][j] = t1;
    }
    __syncwarp();

    // ---- blend + stage ----
    if (lane < 8) {
        #pragma unroll
        for (int m = 0; m < 5; ++m) {
            int j = j0 + m;
            ob[w][0][j] = w1s[j] * a0[m] + w2s[j] * tb[w][0][j];
            ob[w][1][j] = w1s[j] * a1[m] + w2s[j] * tb[w][1][j];
        }
    } else {
        #pragma unroll
        for (int m = 0; m < 5; ++m) {
            int j = j0 + m;
            ob[w][0][j] = a0[m];
            ob[w][1][j] = a1[m];
        }
    }
    __syncwarp();

    // ---- coalesced float4 store ----
    int f = f0 + w;
    #pragma unroll
    for (int co = 0; co < COUT; ++co) {
        float4* op = (float4*)(out + (size_t)b * COUT * NSAMP
                               + (size_t)co * NSAMP + (size_t)f * FRAME);
        const float4* obp = (const float4*)ob[w][co];
        #pragma unroll
        for (int i = lane; i < FRAME / 4; i += 32)
            op[i] = obp[i];
    }
}

extern "C" void kernel_launch(void* const* d_in, const int* in_sizes, int n_in,
                              void* d_out, int out_size)
{
    const float* x    = (const float*)d_in[0];
    const float* feat = (const float*)d_in[1];
    const float* ckw  = (const float*)d_in[2];
    const float* ckb  = (const float*)d_in[3];
    const float* fgw  = (const float*)d_in[4];
    const float* fgb  = (const float*)d_in[5];
    const float* ow   = (const float*)d_in[6];
    float* out = (float*)d_out;

    int smem = (TBF * 260 + 256 * WSTRIDE + 3 * TBF * 2) * (int)sizeof(float);
    static int configured = 0;
    if (!configured) {
        cudaFuncSetAttribute(filt_kernel,
                             cudaFuncAttributeMaxDynamicSharedMemorySize, smem);
        configured = 1;
    }

    filt_kernel<<<NB * NF / TBF, 256, smem>>>(feat, ckw, ckb, fgw, fgb);
    conv_kernel<<<dim3(NF / FPB, NB), FPB * 32>>>(x, ow, out);
}

// round 6
// speedup vs baseline: 1.0503x; 1.0503x over previous
#include <cuda_runtime.h>
#include <math.h>

#define NB    32
#define NF    500
#define FEAT  256
#define COUT  2
#define CIN   2
#define KK    16
#define FRAME 160
#define OVL   40
#define NSAMP (NF * FRAME)          // 80000
#define NFILT (COUT * CIN * KK)     // 64

#define GAIN_A 0.69077552789821368f
#define SG     0.50118723362727224f
#define OMSG   0.49881276637272776f

// Per-frame filters: [(b*NF+f)*64 + cout*32 + cin*16 + k]
__device__ float g_w[(size_t)NB * NF * NFILT];

// ===========================================================================
// Kernel A: filter synthesis GEMM + epilogue (R3 version, known ~20us).
// ===========================================================================
#define TBF 128
#define FSTRIDE4 65
#define WSTRIDE  68

__global__ void __launch_bounds__(256) filt_kernel(
    const float* __restrict__ feat,
    const float* __restrict__ ckw,
    const float* __restrict__ ckb,
    const float* __restrict__ fgw,
    const float* __restrict__ fgb)
{
    extern __shared__ float sm[];
    float*  fs   = sm;                                   // [128][260]
    float*  Wt   = sm + TBF * 260;                       // [256][68]
    float*  gg   = Wt + 256 * WSTRIDE;
    float*  invn = gg + TBF * 2;
    float*  gain = invn + TBF * 2;
    float4* fs4  = (float4*)fs;
    float4* Wt4  = (float4*)Wt;

    int tid = threadIdx.x;
    int bf0 = blockIdx.x * TBF;

    const float4* feat4 = (const float4*)feat;
    for (int i = tid; i < TBF * 64; i += 256) {
        int r = i >> 6, c4 = i & 63;
        fs4[r * FSTRIDE4 + c4] = feat4[(size_t)(bf0 + r) * 64 + c4];
    }
    for (int i = tid; i < 64 * 256; i += 256) {
        int o = i >> 8, fe = i & 255;
        Wt[fe * WSTRIDE + o] = ckw[i];
    }
    {
        int fe = tid;
        Wt[fe * WSTRIDE + 64] = 0.f; Wt[fe * WSTRIDE + 65] = 0.f;
        Wt[fe * WSTRIDE + 66] = 0.f; Wt[fe * WSTRIDE + 67] = 0.f;
    }
    __syncthreads();

    int ogrp = tid & 15;
    int rgrp = tid >> 4;
    int o0 = ogrp * 4;
    int r0 = rgrp * 8;

    float acc[8][4];
    #pragma unroll
    for (int i = 0; i < 8; ++i)
        #pragma unroll
        for (int j = 0; j < 4; ++j) acc[i][j] = 0.f;

    const float4* fsp = fs4 + r0 * FSTRIDE4;
    const float4* wtp = Wt4 + ogrp;

    #pragma unroll 4
    for (int fe4 = 0; fe4 < 64; ++fe4) {
        float4 fv[8];
        #pragma unroll
        for (int i = 0; i < 8; ++i) fv[i] = fsp[i * FSTRIDE4 + fe4];
        float4 w0 = wtp[(4 * fe4 + 0) * 17];
        float4 w1 = wtp[(4 * fe4 + 1) * 17];
        float4 w2 = wtp[(4 * fe4 + 2) * 17];
        float4 w3 = wtp[(4 * fe4 + 3) * 17];
        #pragma unroll
        for (int i = 0; i < 8; ++i) {
            acc[i][0] = fmaf(fv[i].x, w0.x, acc[i][0]);
            acc[i][1] = fmaf(fv[i].x, w0.y, acc[i][1]);
            acc[i][2] = fmaf(fv[i].x, w0.z, acc[i][2]);
            acc[i][3] = fmaf(fv[i].x, w0.w, acc[i][3]);
            acc[i][0] = fmaf(fv[i].y, w1.x, acc[i][0]);
            acc[i][1] = fmaf(fv[i].y, w1.y, acc[i][1]);
            acc[i][2] = fmaf(fv[i].y, w1.z, acc[i][2]);
            acc[i][3] = fmaf(fv[i].y, w1.w, acc[i][3]);
            acc[i][0] = fmaf(fv[i].z, w2.x, acc[i][0]);
            acc[i][1] = fmaf(fv[i].z, w2.y, acc[i][1]);
            acc[i][2] = fmaf(fv[i].z, w2.z, acc[i][2]);
            acc[i][3] = fmaf(fv[i].z, w2.w, acc[i][3]);
            acc[i][0] = fmaf(fv[i].w, w3.x, acc[i][0]);
            acc[i][1] = fmaf(fv[i].w, w3.y, acc[i][1]);
            acc[i][2] = fmaf(fv[i].w, w3.z, acc[i][2]);
            acc[i][3] = fmaf(fv[i].w, w3.w, acc[i][3]);
        }
    }

    {
        int r = tid >> 1, c = tid & 1;
        const float4* fr = fs4 + r * FSTRIDE4;
        const float4* gw = (const float4*)fgw + c * 64;
        float s = 0.f;
        #pragma unroll 4
        for (int fe4 = 0; fe4 < 64; ++fe4) {
            float4 a = fr[fe4];
            float4 b = __ldg(&gw[fe4]);
            s += a.x * b.x + a.y * b.y + a.z * b.z + a.w * b.w;
        }
        gg[r * 2 + c] = s + __ldg(&fgb[c]);
    }
    __syncthreads();

    float* raw = fs;
    #pragma unroll
    for (int i = 0; i < 8; ++i)
        #pragma unroll
        for (int j = 0; j < 4; ++j)
            raw[(r0 + i) * WSTRIDE + (o0 + j)] = acc[i][j] + __ldg(&ckb[o0 + j]);
    __syncthreads();

    {
        int r = tid >> 1, c = tid & 1;
        float ss = 0.f;
        #pragma unroll
        for (int i = 0; i < 32; ++i) {
            float v = raw[r * WSTRIDE + c * 32 + i];
            ss += v * v;
        }
        invn[r * 2 + c] = 1.0f / (1e-6f + sqrtf(ss));
        gain[r * 2 + c] = expf(GAIN_A * tanhf(gg[r * 2 + c]));
    }
    __syncthreads();

    for (int idx = tid; idx < TBF * NFILT; idx += 256) {
        int r = idx >> 6, o = idx & 63;
        int co = o >> 5;
        float v = SG * raw[r * WSTRIDE + o] * invn[r * 2 + co];
        if ((o & 15) == 7) v += OMSG;
        g_w[(size_t)(bf0 + r) * NFILT + o] = v * gain[r * 2 + co];
    }
}

// ===========================================================================
// Kernel B: R3 conv with COOPERATIVE tail.
// Head: lane -> 5 consecutive outputs from 20-float register window, per-cin.
// Tail: round 1 all 32 lanes (j=lane), round 2 lanes 0-7 (j=32+lane); results
// exchanged via smem, blended by lanes 0-7. 448 FFMA warp-slots/frame vs 640.
// FPB=10, 320 threads, 3 blocks/SM.
// ===========================================================================
#define FPB  10
#define NEED (FPB * FRAME + 16)      // 1616
#define XPAD 1624

__global__ void __launch_bounds__(FPB * 32, 3) conv_kernel(
    const float* __restrict__ x,     // (B, CIN, NSAMP)
    const float* __restrict__ owin,  // (40,)
    float* __restrict__ out)         // (B, COUT, NSAMP)
{
    __shared__ __align__(16) float xs[CIN][XPAD];
    __shared__ __align__(16) float wsm[FPB + 1][NFILT];
    __shared__ float tb[FPB][COUT][OVL];
    __shared__ __align__(16) float ob[FPB][COUT][FRAME];
    __shared__ float w1s[OVL], w2s[OVL];

    const int NT = FPB * 32;
    int f0 = blockIdx.x * FPB;
    int b  = blockIdx.y;
    int tid  = threadIdx.x;
    int lane = tid & 31;
    int w    = tid >> 5;

    // ---- x window (float4 coalesced) ----
    const float* xb = x + (size_t)b * CIN * NSAMP;
    if (f0 == 0) {
        if (tid < 16) { xs[0][tid] = 0.f; xs[1][tid] = 0.f; }
        const int N4 = (NEED - 16) / 4;
        for (int i = tid; i < CIN * N4; i += NT) {
            int ci = i / N4, q = i - ci * N4;
            ((float4*)(xs[ci] + 16))[q] =
                ((const float4*)(xb + (size_t)ci * NSAMP))[q];
        }
    } else {
        int base = f0 * FRAME - 16;
        const int N4 = NEED / 4;
        for (int i = tid; i < CIN * N4; i += NT) {
            int ci = i / N4, q = i - ci * N4;
            ((float4*)xs[ci])[q] =
                ((const float4*)(xb + (size_t)ci * NSAMP + base))[q];
        }
    }
    // ---- filters for frames f0-1 .. f0+FPB-1 ----
    for (int i = tid; i < (FPB + 1) * NFILT; i += NT) {
        int fi = f0 - 1 + (i >> 6);
        wsm[0][i] = (fi >= 0) ? g_w[((size_t)b * NF + fi) * NFILT + (i & 63)]
                              : 0.f;
    }
    if (tid < OVL) {
        w2s[tid] = owin[tid];
        w1s[tid] = owin[OVL - 1 - tid];
    }
    __syncthreads();

    int j0 = 5 * lane;
    int sb = w * FRAME + 16;

    float a0[5] = {0,0,0,0,0}, a1[5] = {0,0,0,0,0};
    const float4* wc = (const float4*)wsm[w + 1];
    const float4* wp = (const float4*)wsm[w];

    // ---- head ----
    #pragma unroll
    for (int ci = 0; ci < CIN; ++ci) {
        float xw[20];
        #pragma unroll
        for (int i = 0; i < 20; ++i)
            xw[i] = xs[ci][sb + j0 - 15 + i];
        #pragma unroll
        for (int kc = 0; kc < 4; ++kc) {
            float4 c0 = wc[ci * 4 + kc];
            float4 c1 = wc[8 + ci * 4 + kc];
            float wk0[4] = {c0.x, c0.y, c0.z, c0.w};
            float wk1[4] = {c1.x, c1.y, c1.z, c1.w};
            #pragma unroll
            for (int kk = 0; kk < 4; ++kk) {
                int k = 4 * kc + kk;
                #pragma unroll
                for (int m = 0; m < 5; ++m) {
                    float xv = xw[m + 15 - k];
                    a0[m] = fmaf(wk0[kk], xv, a0[m]);
                    a1[m] = fmaf(wk1[kk], xv, a1[m]);
                }
            }
        }
    }

    // ---- tail round 1: j = lane (all 32 lanes useful) ----
    {
        float t0 = 0.f, t1 = 0.f;
        #pragma unroll
        for (int ci = 0; ci < CIN; ++ci) {
            float tw[16];
            #pragma unroll
            for (int i = 0; i < 16; ++i)
                tw[i] = xs[ci][sb + lane - 15 + i];
            #pragma unroll
            for (int kc = 0; kc < 4; ++kc) {
                float4 c0 = wp[ci * 4 + kc];
                float4 c1 = wp[8 + ci * 4 + kc];
                float wk0[4] = {c0.x, c0.y, c0.z, c0.w};
                float wk1[4] = {c1.x, c1.y, c1.z, c1.w};
                #pragma unroll
                for (int kk = 0; kk < 4; ++kk) {
                    int k = 4 * kc + kk;
                    t0 = fmaf(wk0[kk], tw[15 - k], t0);
                    t1 = fmaf(wk1[kk], tw[15 - k], t1);
                }
            }
        }
        tb[w][0][lane] = t0;
        tb[w][1][lane] = t1;
    }
    // ---- tail round 2: j = 32 + lane (lanes 0-7) ----
    if (lane < 8) {
        int j = 32 + lane;
        float t0 = 0.f, t1 = 0.f;
        #pragma unroll
        for (int ci = 0; ci < CIN; ++ci) {
            float tw[16];
            #pragma unroll
            for (int i = 0; i < 16; ++i)
                tw[i] = xs[ci][sb + j - 15 + i];
            #pragma unroll
            for (int kc = 0; kc < 4; ++kc) {
                float4 c0 = wp[ci * 4 + kc];
                float4 c1 = wp[8 + ci * 4 + kc];
                float wk0[4] = {c0.x, c0.y, c0.z, c0.w};
                float wk1[4] = {c1.x, c1.y, c1.z, c1.w};
                #pragma unroll
                for (int kk = 0; kk < 4; ++kk) {
                    int k = 4 * kc + kk;
                    t0 = fmaf(wk0[kk], tw[15 - k], t0);
                    t1 = fmaf(wk1[kk], tw[15 - k], t1);
                }
            }
        }
        tb[w][0][j] = t0;
        tb[w][1][j] = t1;
    }
    __syncwarp();

    // ---- blend + stage ----
    if (lane < 8) {
        #pragma unroll
        for (int m = 0; m < 5; ++m) {
            int j = j0 + m;
            ob[w][0][j] = w1s[j] * a0[m] + w2s[j] * tb[w][0][j];
            ob[w][1][j] = w1s[j] * a1[m] + w2s[j] * tb[w][1][j];
        }
    } else {
        #pragma unroll
        for (int m = 0; m < 5; ++m) {
            int j = j0 + m;
            ob[w][0][j] = a0[m];
            ob[w][1][j] = a1[m];
        }
    }
    __syncwarp();

    // ---- coalesced float4 store ----
    int f = f0 + w;
    #pragma unroll
    for (int co = 0; co < COUT; ++co) {
        float4* op = (float4*)(out + (size_t)b * COUT * NSAMP
                               + (size_t)co * NSAMP + (size_t)f * FRAME);
        const float4* obp = (const float4*)ob[w][co];
        #pragma unroll
        for (int i = lane; i < FRAME / 4; i += 32)
            op[i] = obp[i];
    }
}

extern "C" void kernel_launch(void* const* d_in, const int* in_sizes, int n_in,
                              void* d_out, int out_size)
{
    const float* x    = (const float*)d_in[0];
    const float* feat = (const float*)d_in[1];
    const float* ckw  = (const float*)d_in[2];
    const float* ckb  = (const float*)d_in[3];
    const float* fgw  = (const float*)d_in[4];
    const float* fgb  = (const float*)d_in[5];
    const float* ow   = (const float*)d_in[6];
    float* out = (float*)d_out;

    int smem = (TBF * 260 + 256 * WSTRIDE + 3 * TBF * 2) * (int)sizeof(float);
    static int configured = 0;
    if (!configured) {
        cudaFuncSetAttribute(filt_kernel,
                             cudaFuncAttributeMaxDynamicSharedMemorySize, smem);
        configured = 1;
    }

    filt_kernel<<<NB * NF / TBF, 256, smem>>>(feat, ckw, ckb, fgw, fgb);
    conv_kernel<<<dim3(NF / FPB, NB), FPB * 32>>>(x, ow, out);
}

// round 7
// speedup vs baseline: 1.2301x; 1.1712x over previous
#include <cuda_runtime.h>
#include <math.h>

#define NB    32
#define NF    500
#define FEAT  256
#define COUT  2
#define CIN   2
#define KK    16
#define FRAME 160
#define OVL   40
#define NSAMP (NF * FRAME)          // 80000
#define NFILT (COUT * CIN * KK)     // 64

#define GAIN_A 0.69077552789821368f
#define SG     0.50118723362727224f
#define OMSG   0.49881276637272776f

// Per-frame filters: [(b*NF+f)*64 + cout*32 + cin*16 + k]
__device__ float g_w[(size_t)NB * NF * NFILT];

// ===========================================================================
// Kernel A: filter synthesis GEMM + epilogue (R3 version, ~20us, near its
// scalar FFMA floor — do not touch until tensor-core rewrite).
// ===========================================================================
#define TBF 128
#define FSTRIDE4 65
#define WSTRIDE  68

__global__ void __launch_bounds__(256) filt_kernel(
    const float* __restrict__ feat,
    const float* __restrict__ ckw,
    const float* __restrict__ ckb,
    const float* __restrict__ fgw,
    const float* __restrict__ fgb)
{
    extern __shared__ float sm[];
    float*  fs   = sm;                                   // [128][260]
    float*  Wt   = sm + TBF * 260;                       // [256][68]
    float*  gg   = Wt + 256 * WSTRIDE;
    float*  invn = gg + TBF * 2;
    float*  gain = invn + TBF * 2;
    float4* fs4  = (float4*)fs;
    float4* Wt4  = (float4*)Wt;

    int tid = threadIdx.x;
    int bf0 = blockIdx.x * TBF;

    const float4* feat4 = (const float4*)feat;
    for (int i = tid; i < TBF * 64; i += 256) {
        int r = i >> 6, c4 = i & 63;
        fs4[r * FSTRIDE4 + c4] = feat4[(size_t)(bf0 + r) * 64 + c4];
    }
    for (int i = tid; i < 64 * 256; i += 256) {
        int o = i >> 8, fe = i & 255;
        Wt[fe * WSTRIDE + o] = ckw[i];
    }
    {
        int fe = tid;
        Wt[fe * WSTRIDE + 64] = 0.f; Wt[fe * WSTRIDE + 65] = 0.f;
        Wt[fe * WSTRIDE + 66] = 0.f; Wt[fe * WSTRIDE + 67] = 0.f;
    }
    __syncthreads();

    int ogrp = tid & 15;
    int rgrp = tid >> 4;
    int o0 = ogrp * 4;
    int r0 = rgrp * 8;

    float acc[8][4];
    #pragma unroll
    for (int i = 0; i < 8; ++i)
        #pragma unroll
        for (int j = 0; j < 4; ++j) acc[i][j] = 0.f;

    const float4* fsp = fs4 + r0 * FSTRIDE4;
    const float4* wtp = Wt4 + ogrp;

    #pragma unroll 4
    for (int fe4 = 0; fe4 < 64; ++fe4) {
        float4 fv[8];
        #pragma unroll
        for (int i = 0; i < 8; ++i) fv[i] = fsp[i * FSTRIDE4 + fe4];
        float4 w0 = wtp[(4 * fe4 + 0) * 17];
        float4 w1 = wtp[(4 * fe4 + 1) * 17];
        float4 w2 = wtp[(4 * fe4 + 2) * 17];
        float4 w3 = wtp[(4 * fe4 + 3) * 17];
        #pragma unroll
        for (int i = 0; i < 8; ++i) {
            acc[i][0] = fmaf(fv[i].x, w0.x, acc[i][0]);
            acc[i][1] = fmaf(fv[i].x, w0.y, acc[i][1]);
            acc[i][2] = fmaf(fv[i].x, w0.z, acc[i][2]);
            acc[i][3] = fmaf(fv[i].x, w0.w, acc[i][3]);
            acc[i][0] = fmaf(fv[i].y, w1.x, acc[i][0]);
            acc[i][1] = fmaf(fv[i].y, w1.y, acc[i][1]);
            acc[i][2] = fmaf(fv[i].y, w1.z, acc[i][2]);
            acc[i][3] = fmaf(fv[i].y, w1.w, acc[i][3]);
            acc[i][0] = fmaf(fv[i].z, w2.x, acc[i][0]);
            acc[i][1] = fmaf(fv[i].z, w2.y, acc[i][1]);
            acc[i][2] = fmaf(fv[i].z, w2.z, acc[i][2]);
            acc[i][3] = fmaf(fv[i].z, w2.w, acc[i][3]);
            acc[i][0] = fmaf(fv[i].w, w3.x, acc[i][0]);
            acc[i][1] = fmaf(fv[i].w, w3.y, acc[i][1]);
            acc[i][2] = fmaf(fv[i].w, w3.z, acc[i][2]);
            acc[i][3] = fmaf(fv[i].w, w3.w, acc[i][3]);
        }
    }

    {
        int r = tid >> 1, c = tid & 1;
        const float4* fr = fs4 + r * FSTRIDE4;
        const float4* gw = (const float4*)fgw + c * 64;
        float s = 0.f;
        #pragma unroll 4
        for (int fe4 = 0; fe4 < 64; ++fe4) {
            float4 a = fr[fe4];
            float4 b = __ldg(&gw[fe4]);
            s += a.x * b.x + a.y * b.y + a.z * b.z + a.w * b.w;
        }
        gg[r * 2 + c] = s + __ldg(&fgb[c]);
    }
    __syncthreads();

    float* raw = fs;
    #pragma unroll
    for (int i = 0; i < 8; ++i)
        #pragma unroll
        for (int j = 0; j < 4; ++j)
            raw[(r0 + i) * WSTRIDE + (o0 + j)] = acc[i][j] + __ldg(&ckb[o0 + j]);
    __syncthreads();

    {
        int r = tid >> 1, c = tid & 1;
        float ss = 0.f;
        #pragma unroll
        for (int i = 0; i < 32; ++i) {
            float v = raw[r * WSTRIDE + c * 32 + i];
            ss += v * v;
        }
        invn[r * 2 + c] = 1.0f / (1e-6f + sqrtf(ss));
        gain[r * 2 + c] = expf(GAIN_A * tanhf(gg[r * 2 + c]));
    }
    __syncthreads();

    for (int idx = tid; idx < TBF * NFILT; idx += 256) {
        int r = idx >> 6, o = idx & 63;
        int co = o >> 5;
        float v = SG * raw[r * WSTRIDE + o] * invn[r * 2 + co];
        if ((o & 15) == 7) v += OMSG;
        g_w[(size_t)(bf0 + r) * NFILT + o] = v * gain[r * 2 + co];
    }
}

// ===========================================================================
// Kernel B: R3 conv formulation (best known: predicated tail reusing the
// register window), re-shaped for occupancy: FPB=5, 160-thread blocks,
// __launch_bounds__(160, 8) -> 40 warps/SM ceiling (vs 30).
// ===========================================================================
#define FPB  5
#define NEED (FPB * FRAME + 16)      // 816
#define XPAD 824

__global__ void __launch_bounds__(FPB * 32, 8) conv_kernel(
    const float* __restrict__ x,     // (B, CIN, NSAMP)
    const float* __restrict__ owin,  // (40,)
    float* __restrict__ out)         // (B, COUT, NSAMP)
{
    __shared__ __align__(16) float xs[CIN][XPAD];         // origin f0*160-16
    __shared__ __align__(16) float wsm[FPB + 1][NFILT];   // [0] = f0-1 filter
    __shared__ __align__(16) float ob[FPB][COUT][FRAME];
    __shared__ float w1s[OVL], w2s[OVL];

    const int NT = FPB * 32;
    int f0 = blockIdx.x * FPB;
    int b  = blockIdx.y;
    int tid  = threadIdx.x;
    int lane = tid & 31;
    int w    = tid >> 5;

    // ---- x window (float4 coalesced) ----
    const float* xb = x + (size_t)b * CIN * NSAMP;
    if (f0 == 0) {
        if (tid < 16) { xs[0][tid] = 0.f; xs[1][tid] = 0.f; }
        const int N4 = (NEED - 16) / 4;                   // 200
        for (int i = tid; i < CIN * N4; i += NT) {
            int ci = i / N4, q = i - ci * N4;
            ((float4*)(xs[ci] + 16))[q] =
                ((const float4*)(xb + (size_t)ci * NSAMP))[q];
        }
    } else {
        int base = f0 * FRAME - 16;                       // 16B-aligned
        const int N4 = NEED / 4;                          // 204
        for (int i = tid; i < CIN * N4; i += NT) {
            int ci = i / N4, q = i - ci * N4;
            ((float4*)xs[ci])[q] =
                ((const float4*)(xb + (size_t)ci * NSAMP + base))[q];
        }
    }
    // ---- filters for frames f0-1 .. f0+FPB-1 ----
    for (int i = tid; i < (FPB + 1) * NFILT; i += NT) {
        int fi = f0 - 1 + (i >> 6);
        wsm[0][i] = (fi >= 0) ? g_w[((size_t)b * NF + fi) * NFILT + (i & 63)]
                              : 0.f;
    }
    if (tid < OVL) {
        w2s[tid] = owin[tid];
        w1s[tid] = owin[OVL - 1 - tid];
    }
    __syncthreads();

    int j0 = 5 * lane;
    int sb = w * FRAME + 16;          // xs index of this frame's sample 0

    float a0[5] = {0,0,0,0,0}, a1[5] = {0,0,0,0,0};
    float p0[5] = {0,0,0,0,0}, p1[5] = {0,0,0,0,0};

    const float4* wc = (const float4*)wsm[w + 1];
    const float4* wp = (const float4*)wsm[w];

    #pragma unroll
    for (int ci = 0; ci < CIN; ++ci) {
        float xw[20];
        #pragma unroll
        for (int i = 0; i < 20; ++i)
            xw[i] = xs[ci][sb + j0 - 15 + i];

        #pragma unroll
        for (int kc = 0; kc < 4; ++kc) {
            float4 c0 = wc[ci * 4 + kc];          // co=0, taps 4kc..4kc+3
            float4 c1 = wc[8 + ci * 4 + kc];      // co=1
            float wk0[4] = {c0.x, c0.y, c0.z, c0.w};
            float wk1[4] = {c1.x, c1.y, c1.z, c1.w};
            #pragma unroll
            for (int kk = 0; kk < 4; ++kk) {
                int k = 4 * kc + kk;
                #pragma unroll
                for (int m = 0; m < 5; ++m) {
                    float xv = xw[m + 15 - k];
                    a0[m] = fmaf(wk0[kk], xv, a0[m]);
                    a1[m] = fmaf(wk1[kk], xv, a1[m]);
                }
            }
        }
        if (lane < 8) {                            // overlap lanes: tail conv
            #pragma unroll
            for (int kc = 0; kc < 4; ++kc) {
                float4 c0 = wp[ci * 4 + kc];
                float4 c1 = wp[8 + ci * 4 + kc];
                float wk0[4] = {c0.x, c0.y, c0.z, c0.w};
                float wk1[4] = {c1.x, c1.y, c1.z, c1.w};
                #pragma unroll
                for (int kk = 0; kk < 4; ++kk) {
                    int k = 4 * kc + kk;
                    #pragma unroll
                    for (int m = 0; m < 5; ++m) {
                        float xv = xw[m + 15 - k];
                        p0[m] = fmaf(wk0[kk], xv, p0[m]);
                        p1[m] = fmaf(wk1[kk], xv, p1[m]);
                    }
                }
            }
        }
    }

    // ---- blend + stage ----
    if (lane < 8) {
        #pragma unroll
        for (int m = 0; m < 5; ++m) {
            int j = j0 + m;
            ob[w][0][j] = w1s[j] * a0[m] + w2s[j] * p0[m];
            ob[w][1][j] = w1s[j] * a1[m] + w2s[j] * p1[m];
        }
    } else {
        #pragma unroll
        for (int m = 0; m < 5; ++m) {
            int j = j0 + m;
            ob[w][0][j] = a0[m];
            ob[w][1][j] = a1[m];
        }
    }
    __syncwarp();

    // ---- coalesced float4 store ----
    int f = f0 + w;
    #pragma unroll
    for (int co = 0; co < COUT; ++co) {
        float4* op = (float4*)(out + (size_t)b * COUT * NSAMP
                               + (size_t)co * NSAMP + (size_t)f * FRAME);
        const float4* obp = (const float4*)ob[w][co];
        #pragma unroll
        for (int i = lane; i < FRAME / 4; i += 32)
            op[i] = obp[i];
    }
}

extern "C" void kernel_launch(void* const* d_in, const int* in_sizes, int n_in,
                              void* d_out, int out_size)
{
    const float* x    = (const float*)d_in[0];
    const float* feat = (const float*)d_in[1];
    const float* ckw  = (const float*)d_in[2];
    const float* ckb  = (const float*)d_in[3];
    const float* fgw  = (const float*)d_in[4];
    const float* fgb  = (const float*)d_in[5];
    const float* ow   = (const float*)d_in[6];
    float* out = (float*)d_out;

    int smem = (TBF * 260 + 256 * WSTRIDE + 3 * TBF * 2) * (int)sizeof(float);
    static int configured = 0;
    if (!configured) {
        cudaFuncSetAttribute(filt_kernel,
                             cudaFuncAttributeMaxDynamicSharedMemorySize, smem);
        configured = 1;
    }

    filt_kernel<<<NB * NF / TBF, 256, smem>>>(feat, ckw, ckb, fgw, fgb);
    conv_kernel<<<dim3(NF / FPB, NB), FPB * 32>>>(x, ow, out);
}